// round 15
// baseline (speedup 1.0000x reference)
#include <cuda_runtime.h>
#include <cuda_bf16.h>
#include <cstdint>

#define NROWS  100000
#define DIM    128
#define BTOT   500000
#define KTOT   384
#define DOUT   128

#if defined(__CUDA_ARCH__) && (defined(__CUDA_ARCH_FEAT_SM103_ALL) || defined(__CUDA_ARCH_FEAT_SM100_ALL))
#define HAS_TCGEN05 1
#else
#define HAS_TCGEN05 0
#endif

// ---------------- device scratch ----------------
__device__ __nv_bfloat16 g_xb[(size_t)NROWS * DIM];
__device__ __nv_bfloat16 g_wtb[DOUT * KTOT];
__device__ float g_partial[1024][DIM];
__device__ float g_pool[DOUT];

// ---------------- helpers ----------------
__device__ __forceinline__ uint32_t smem_u32(const void* p) {
    uint32_t a;
    asm("{ .reg .u64 t; cvta.to.shared.u64 t, %1; cvt.u32.u64 %0, t; }" : "=r"(a) : "l"(p));
    return a;
}
#define SW128(o) ((o) ^ (((o) >> 3) & 0x70))

// streaming (evict-first policy) 128-bit store — output never needed again
__device__ __forceinline__ void stg_cs(float* p, float4 v) {
    asm volatile("st.global.cs.v4.f32 [%0], {%1,%2,%3,%4};"
                 :: "l"(p), "f"(v.x), "f"(v.y), "f"(v.z), "f"(v.w) : "memory");
}

// evict_last policy: keep x pinned in L2 across its ~15x reuse
__device__ __forceinline__ uint64_t make_evict_last_policy() {
    uint64_t pol;
    asm("createpolicy.fractional.L2::evict_last.b64 %0, 1.0;" : "=l"(pol));
    return pol;
}
__device__ __forceinline__ uint4 ldg_evict_last(const void* p, uint64_t pol) {
    uint4 v;
    asm volatile("ld.global.L2::cache_hint.v4.u32 {%0,%1,%2,%3}, [%4], %5;"
                 : "=r"(v.x), "=r"(v.y), "=r"(v.z), "=r"(v.w)
                 : "l"(p), "l"(pol));
    return v;
}

#if HAS_TCGEN05

__device__ __forceinline__ bool elect_one() {
    uint32_t pred;
    asm volatile("{ .reg .pred p; elect.sync _|p, 0xFFFFFFFF; selp.b32 %0, 1, 0, p; }" : "=r"(pred));
    return pred != 0;
}

static constexpr uint64_t DESC_BASE_SW128 =
    (uint64_t(2) << 61) | (uint64_t(1) << 46) | (uint64_t(64) << 32) | (uint64_t(1) << 16);
__device__ __forceinline__ uint64_t make_desc(uint32_t addr) {
    return DESC_BASE_SW128 | ((uint64_t)(addr >> 4) & 0x3FFF);
}

__device__ __forceinline__ void mma_f16_ss(uint32_t d, uint64_t ad, uint64_t bd,
                                           uint32_t idesc, bool acc) {
    uint32_t e = acc ? 1u : 0u;
    asm volatile(
        "{\n\t.reg .pred p;\n\tsetp.ne.u32 p, %4, 0;\n\t"
        "tcgen05.mma.cta_group::1.kind::f16 [%0], %1, %2, %3, {%5, %5, %5, %5}, p;\n\t}"
        :: "r"(d), "l"(ad), "l"(bd), "r"(idesc), "r"(e), "r"(0u) : "memory");
}

#define TC_ALLOC(smem_addr, ncols) \
    asm volatile("tcgen05.alloc.cta_group::1.sync.aligned.shared::cta.b32 [%0], %1;" \
                 :: "r"(smem_addr), "r"((uint32_t)(ncols)) : "memory")
#define TC_RELINQ() \
    asm volatile("tcgen05.relinquish_alloc_permit.cta_group::1.sync.aligned;")
#define TC_DEALLOC(tmem, ncols) \
    asm volatile("tcgen05.dealloc.cta_group::1.sync.aligned.b32 %0, %1;" \
                 :: "r"(tmem), "r"((uint32_t)(ncols)))
#define TC_COMMIT(mbar) \
    asm volatile("tcgen05.commit.cta_group::1.mbarrier::arrive::one.shared::cluster.b64 [%0];" \
                 :: "r"(mbar) : "memory")
#define TC_FENCE_AFTER()  asm volatile("tcgen05.fence::after_thread_sync;" ::: "memory")
#define TC_FENCE_BEFORE() asm volatile("tcgen05.fence::before_thread_sync;" ::: "memory")
#define TC_WAIT_LD()      asm volatile("tcgen05.wait::ld.sync.aligned;" ::: "memory")
#define FENCE_PROXY()     asm volatile("fence.proxy.async.shared::cta;" ::: "memory")
#define MBAR_INIT(a, n) \
    asm volatile("mbarrier.init.shared.b64 [%0], %1;" :: "r"(a), "r"((uint32_t)(n)) : "memory")
#define MBAR_INVAL(a) \
    asm volatile("mbarrier.inval.shared.b64 [%0];" :: "r"(a) : "memory")

#define MBAR_WAIT(mbar_addr, parity) do {                                         \
    uint32_t _m = (mbar_addr); uint32_t _p = (parity); uint32_t _d;               \
    asm volatile("{\n\t.reg .pred p;\n\t"                                         \
        "mbarrier.try_wait.parity.acquire.cta.shared::cta.b64 p, [%1], %2;\n\t"   \
        "selp.b32 %0, 1, 0, p;\n\t}" : "=r"(_d) : "r"(_m), "r"(_p) : "memory");   \
    if (!_d) {                                                                    \
        asm volatile("{\n\t.reg .pred P1;\n\t"                                    \
            "WL_%=:\n\t"                                                          \
            "mbarrier.try_wait.parity.acquire.cta.shared::cta.b64 P1, [%0], %1, 0x989680;\n\t" \
            "@P1 bra.uni WD_%=;\n\t"                                              \
            "bra.uni WL_%=;\n\t"                                                  \
            "WD_%=:\n\t}" :: "r"(_m), "r"(_p) : "memory");                        \
    }                                                                             \
} while (0)

#define LDTM_X32(r, tmem_addr)                                                    \
    asm volatile("tcgen05.ld.sync.aligned.32x32b.x32.b32 "                        \
        "{%0, %1, %2, %3, %4, %5, %6, %7, %8, %9, %10, %11, %12, %13, %14, %15, " \
        " %16, %17, %18, %19, %20, %21, %22, %23, %24, %25, %26, %27, %28, %29, %30, %31}, [%32];" \
        : "=r"((r)[0]),  "=r"((r)[1]),  "=r"((r)[2]),  "=r"((r)[3]),              \
          "=r"((r)[4]),  "=r"((r)[5]),  "=r"((r)[6]),  "=r"((r)[7]),              \
          "=r"((r)[8]),  "=r"((r)[9]),  "=r"((r)[10]), "=r"((r)[11]),             \
          "=r"((r)[12]), "=r"((r)[13]), "=r"((r)[14]), "=r"((r)[15]),             \
          "=r"((r)[16]), "=r"((r)[17]), "=r"((r)[18]), "=r"((r)[19]),             \
          "=r"((r)[20]), "=r"((r)[21]), "=r"((r)[22]), "=r"((r)[23]),             \
          "=r"((r)[24]), "=r"((r)[25]), "=r"((r)[26]), "=r"((r)[27]),             \
          "=r"((r)[28]), "=r"((r)[29]), "=r"((r)[30]), "=r"((r)[31])              \
        : "r"(tmem_addr))

#endif // HAS_TCGEN05

// ---------------- prep: x->bf16 + column partials, and W^T ----------------
__global__ void k_prep(const float* __restrict__ x, const float* __restrict__ w) {
    if (blockIdx.x < 1024) {
        int c = threadIdx.x;                 // 0..127
        int blk = blockIdx.x;
        int r0 = blk * 98;
        int r1 = r0 + 98; if (r1 > NROWS) r1 = NROWS;
        float acc = 0.f;
        #pragma unroll 4
        for (int r = r0; r < r1; ++r) {
            float v = x[(size_t)r * DIM + c];
            acc += v;
            g_xb[(size_t)r * DIM + c] = __float2bfloat16(v);
        }
        g_partial[blk][c] = acc;
    } else {
        int base = (blockIdx.x - 1024) * 4096;           // 12 blocks cover 49152
        for (int j = threadIdx.x; j < 4096; j += 128) {
            int i = base + j;
            int n = i / KTOT, k = i - n * KTOT;
            g_wtb[i] = __float2bfloat16(w[(size_t)k * DOUT + n]);
        }
    }
}

// ---------------- pool row ----------------
__global__ void k_pool2(const float* __restrict__ w) {
    __shared__ float red[128];
    int n = blockIdx.x, d = threadIdx.x;
    float s = 0.f;
    #pragma unroll 8
    for (int b = 0; b < 1024; ++b) s += g_partial[b][d];
    red[d] = s * w[(size_t)(KTOT + d) * DOUT + n];
    __syncthreads();
    if (d == 0) {
        float t = 0.f;
        #pragma unroll 8
        for (int i = 0; i < 128; ++i) t += red[i];
        g_pool[n] = t;
    }
}

// ---------------- main persistent pipelined gather-GEMM ----------------
#define SMEM_TMEM  0
#define SMEM_MBAR  8
#define SMEM_POOL  64
#define SMEM_IDX   1024
#define SMEM_A     4096
#define CHUNK_B    16384
#define SMEM_W     (SMEM_A + 6 * CHUNK_B)     // 102400
#define SMEM_STAGE (SMEM_W + 6 * CHUNK_B)     // 200704, 16KB staging
#define SMEM_END   (SMEM_STAGE + 16384)       // 217088
#define DYN_SMEM   (SMEM_END + 1024)

static constexpr uint32_t IDESC_F16 =
    (1u << 4) | (1u << 7) | (1u << 10) | ((DOUT / 8) << 17) | ((128 / 16) << 24);

#if HAS_TCGEN05
__device__ __forceinline__ void stage_idx(char* sm, const int* __restrict__ idx,
                                          long long tile, int tid) {
    for (int i = tid; i < 384; i += 256) {
        int m = i / 3, s = i - m * 3;
        long long b = tile * 128 + m;
        if (b >= BTOT) b = BTOT - 1;
        int v = idx[b * 3 + s];
        if (v < 0) v = 0;
        if (v >= NROWS) v = NROWS - 1;
        *(int*)(sm + SMEM_IDX + i * 4) = v;
    }
}

__device__ __forceinline__ void issue_gathers(const int* sidx, uint4* gv,
                                              int wid, int half, int hl,
                                              uint64_t pol) {
    #pragma unroll
    for (int s = 0; s < 3; ++s)
        #pragma unroll
        for (int it = 0; it < 8; ++it) {
            int m = (wid + it * 8) * 2 + half;
            int xr = sidx[m * 3 + s];
            gv[s * 8 + it] =
                ldg_evict_last((const char*)g_xb + (size_t)xr * 256 + hl * 16, pol);
        }
}

// Epilogue for one finished tile: 4 column-blocks of 32, via 16KB staging.
__device__ __forceinline__ void do_epilogue(char* sm, uint32_t dbase,
                                            long long tile, float* __restrict__ out,
                                            int tid) {
    float4* stg = (float4*)(sm + SMEM_STAGE);
    const float* spool = (const float*)(sm + SMEM_POOL);
    const int c4 = tid & 7, rb = tid >> 3;
    #pragma unroll
    for (int b = 0; b < 4; ++b) {
        const int base = b * 32;
        if (tid < 128) {
            uint32_t r[32];
            LDTM_X32(r, dbase + base);
            TC_WAIT_LD();
            #pragma unroll
            for (int c = 0; c < 32; c += 4) {
                float4 o;
                o.x = __uint_as_float(r[c + 0]);
                o.y = __uint_as_float(r[c + 1]);
                o.z = __uint_as_float(r[c + 2]);
                o.w = __uint_as_float(r[c + 3]);
                stg[(tid << 3) + ((c >> 2) ^ (tid & 7))] = o;
            }
        }
        __syncthreads();
        float4 pv = *(const float4*)(spool + base + c4 * 4);
        #pragma unroll
        for (int j = 0; j < 4; ++j) {
            int row = rb + j * 32;
            long long brow = tile * 128 + row;
            if (brow < BTOT) {
                float4 v = stg[(row << 3) + (c4 ^ (row & 7))];
                v.x += pv.x; v.y += pv.y; v.z += pv.z; v.w += pv.w;
                stg_cs(out + brow * 128 + base + c4 * 4, v);
            }
        }
        __syncthreads();
    }
    if (tid < 128) TC_FENCE_BEFORE();
}
#endif

__global__ void __launch_bounds__(256, 1) __cluster_dims__(1, 1, 1)
k_main(const int* __restrict__ idx, float* __restrict__ out) {
#if HAS_TCGEN05
    extern __shared__ char smraw[];
    uint32_t sb0 = smem_u32(smraw);
    uint32_t sb = (sb0 + 1023u) & ~1023u;
    char* sm = smraw + (sb - sb0);
    int tid = threadIdx.x, wid = tid >> 5, lane = tid & 31;

    if (wid == 0) TC_ALLOC(sb + SMEM_TMEM, 512);
    else          TC_RELINQ();
    if (tid == 0) MBAR_INIT(sb + SMEM_MBAR, 1);
    if (tid < DOUT) *(float*)(sm + SMEM_POOL + tid * 4) = g_pool[tid];

    // Stage weights once: SW128 into 6 K-chunks
    for (int u = tid; u < 6144; u += 256) {
        int n = u / 48;
        int q = u - n * 48;
        int k = q * 8;
        int kc = k >> 6, kin = k & 63;
        uint4 v = *(const uint4*)((const char*)g_wtb + ((size_t)n * KTOT + k) * 2);
        uint32_t off = (uint32_t)n * 128 + (uint32_t)kin * 2;
        *(uint4*)(sm + SMEM_W + kc * CHUNK_B + SW128(off)) = v;
    }
    __syncthreads();
    uint32_t tmem_base = *(volatile uint32_t*)(sm + SMEM_TMEM);
    const int* sidx = (const int*)(sm + SMEM_IDX);
    const uint64_t pol = make_evict_last_policy();

    const int n_tiles = (BTOT + 127) >> 7;         // 3907
    int phase = 0;
    int bufp = 0;
    long long prev_tile = -1;
    int prevp = 0;

    const int half = lane >> 4, hl = lane & 15;
    const int kc_off = hl >> 3;
    const uint32_t colb = (uint32_t)(hl & 7) * 16;

    uint4 gv[24];

    // ---- prologue: stage idx + issue gathers for first tile ----
    long long tile = blockIdx.x;
    if (tile < n_tiles) {
        stage_idx(sm, idx, tile, tid);
        __syncthreads();
        issue_gathers(sidx, gv, wid, half, hl, pol);
    }

    for (; tile < n_tiles; tile += gridDim.x) {
        long long next = tile + gridDim.x;

        // ---- 1. wait previous MMA (frees A, readies D[prevp]) ----
        if (prev_tile >= 0) {
            MBAR_WAIT(sb + SMEM_MBAR, phase);
            phase ^= 1;
            TC_FENCE_AFTER();
        }

        // ---- 2. STS gather regs -> A (swizzled) ----
        #pragma unroll
        for (int s = 0; s < 3; ++s)
            #pragma unroll
            for (int it = 0; it < 8; ++it) {
                int m = (wid + it * 8) * 2 + half;
                uint32_t off = (uint32_t)m * 128 + colb;
                *(uint4*)(sm + SMEM_A + (2 * s + kc_off) * CHUNK_B + SW128(off)) =
                    gv[s * 8 + it];
            }
        __syncthreads();   // also orders prior gather-issues before idx overwrite

        // ---- 3. issue all 24 MMAs into D[bufp]; commit ----
        if (wid == 0 && elect_one()) {
            FENCE_PROXY();
            bool acc = false;
            #pragma unroll
            for (int kc = 0; kc < 6; ++kc) {
                uint64_t ad = make_desc(sb + SMEM_A + kc * CHUNK_B);
                uint64_t bd = make_desc(sb + SMEM_W + kc * CHUNK_B);
                #pragma unroll
                for (int ks = 0; ks < 4; ++ks) {
                    mma_f16_ss(tmem_base + bufp * 128, ad + ks * 2, bd + ks * 2,
                               IDESC_F16, acc);
                    acc = true;
                }
            }
            TC_COMMIT(sb + SMEM_MBAR);
        }

        // ---- 4. stage idx(next) + issue gathers(next); flight covered by epilogue ----
        if (next < n_tiles) {
            stage_idx(sm, idx, next, tid);
            __syncthreads();
            issue_gathers(sidx, gv, wid, half, hl, pol);
        }

        // ---- 5. epilogue of previous tile (overlaps MMA + gather flight) ----
        if (prev_tile >= 0)
            do_epilogue(sm, tmem_base + prevp * 128, prev_tile, out, tid);

        prev_tile = tile;
        prevp = bufp;
        bufp ^= 1;
    }

    // ---- drain last tile ----
    if (prev_tile >= 0) {
        MBAR_WAIT(sb + SMEM_MBAR, phase);
        phase ^= 1;
        TC_FENCE_AFTER();
        do_epilogue(sm, tmem_base + prevp * 128, prev_tile, out, tid);
    }

    __syncthreads();
    if (tid == 0) MBAR_INVAL(sb + SMEM_MBAR);
    __syncthreads();
    if (wid == 0) TC_DEALLOC(tmem_base, 512);
#endif // HAS_TCGEN05
}

// ---------------- launcher ----------------
extern "C" void kernel_launch(void* const* d_in, const int* in_sizes, int n_in,
                              void* d_out, int out_size) {
    const float* x = nullptr;
    const int* idx = nullptr;
    const float* w = nullptr;
    for (int i = 0; i < n_in; ++i) {
        if (in_sizes[i] == NROWS * DIM)              x   = (const float*)d_in[i];
        else if (in_sizes[i] == BTOT * 3)            idx = (const int*)d_in[i];
        else if (in_sizes[i] == (KTOT + DIM) * DOUT) w   = (const float*)d_in[i];
    }
    float* out = (float*)d_out;

    cudaFuncSetAttribute(k_main, cudaFuncAttributeMaxDynamicSharedMemorySize, DYN_SMEM);
    int nsm = 148;
    cudaDeviceGetAttribute(&nsm, cudaDevAttrMultiProcessorCount, 0);

    k_prep<<<1036, 128>>>(x, w);
    k_pool2<<<128, 128>>>(w);
    k_main<<<nsm, 256, DYN_SMEM>>>(idx, out);
}

// round 17
// speedup vs baseline: 1.1628x; 1.1628x over previous
#include <cuda_runtime.h>
#include <cuda.h>
#include <cuda_bf16.h>
#include <cstdint>

#define NROWS  100000
#define DIM    128
#define BTOT   500000
#define KTOT   384
#define DOUT   128

#if defined(__CUDA_ARCH__) && (defined(__CUDA_ARCH_FEAT_SM103_ALL) || defined(__CUDA_ARCH_FEAT_SM100_ALL))
#define HAS_TCGEN05 1
#else
#define HAS_TCGEN05 0
#endif

// ---------------- device scratch ----------------
__device__ __nv_bfloat16 g_xb[(size_t)NROWS * DIM];
__device__ __nv_bfloat16 g_wtb[DOUT * KTOT];
__device__ float g_partial[1024][DIM];
__device__ float g_pool[DOUT];

// ---------------- helpers ----------------
__device__ __forceinline__ uint32_t smem_u32(const void* p) {
    uint32_t a;
    asm("{ .reg .u64 t; cvta.to.shared.u64 t, %1; cvt.u32.u64 %0, t; }" : "=r"(a) : "l"(p));
    return a;
}
#define SW128(o) ((o) ^ (((o) >> 3) & 0x70))

#if HAS_TCGEN05

__device__ __forceinline__ bool elect_one() {
    uint32_t pred;
    asm volatile("{ .reg .pred p; elect.sync _|p, 0xFFFFFFFF; selp.b32 %0, 1, 0, p; }" : "=r"(pred));
    return pred != 0;
}

static constexpr uint64_t DESC_BASE_SW128 =
    (uint64_t(2) << 61) | (uint64_t(1) << 46) | (uint64_t(64) << 32) | (uint64_t(1) << 16);
__device__ __forceinline__ uint64_t make_desc(uint32_t addr) {
    return DESC_BASE_SW128 | ((uint64_t)(addr >> 4) & 0x3FFF);
}

__device__ __forceinline__ void mma_f16_ss(uint32_t d, uint64_t ad, uint64_t bd,
                                           uint32_t idesc, bool acc) {
    uint32_t e = acc ? 1u : 0u;
    asm volatile(
        "{\n\t.reg .pred p;\n\tsetp.ne.u32 p, %4, 0;\n\t"
        "tcgen05.mma.cta_group::1.kind::f16 [%0], %1, %2, %3, {%5, %5, %5, %5}, p;\n\t}"
        :: "r"(d), "l"(ad), "l"(bd), "r"(idesc), "r"(e), "r"(0u) : "memory");
}

#define TC_ALLOC(smem_addr, ncols) \
    asm volatile("tcgen05.alloc.cta_group::1.sync.aligned.shared::cta.b32 [%0], %1;" \
                 :: "r"(smem_addr), "r"((uint32_t)(ncols)) : "memory")
#define TC_RELINQ() \
    asm volatile("tcgen05.relinquish_alloc_permit.cta_group::1.sync.aligned;")
#define TC_DEALLOC(tmem, ncols) \
    asm volatile("tcgen05.dealloc.cta_group::1.sync.aligned.b32 %0, %1;" \
                 :: "r"(tmem), "r"((uint32_t)(ncols)))
#define TC_COMMIT(mbar) \
    asm volatile("tcgen05.commit.cta_group::1.mbarrier::arrive::one.shared::cluster.b64 [%0];" \
                 :: "r"(mbar) : "memory")
#define TC_FENCE_AFTER()  asm volatile("tcgen05.fence::after_thread_sync;" ::: "memory")
#define TC_FENCE_BEFORE() asm volatile("tcgen05.fence::before_thread_sync;" ::: "memory")
#define TC_WAIT_LD()      asm volatile("tcgen05.wait::ld.sync.aligned;" ::: "memory")
#define FENCE_PROXY()     asm volatile("fence.proxy.async.shared::cta;" ::: "memory")
#define MBAR_INIT(a, n) \
    asm volatile("mbarrier.init.shared.b64 [%0], %1;" :: "r"(a), "r"((uint32_t)(n)) : "memory")
#define MBAR_INVAL(a) \
    asm volatile("mbarrier.inval.shared.b64 [%0];" :: "r"(a) : "memory")

#define TMA_WAIT1() asm volatile("cp.async.bulk.wait_group 1;" ::: "memory")
#define TMA_WAIT0() asm volatile("cp.async.bulk.wait_group 0;" ::: "memory")
#define TMA_COMMIT() asm volatile("cp.async.bulk.commit_group;" ::: "memory")

#define MBAR_WAIT(mbar_addr, parity) do {                                         \
    uint32_t _m = (mbar_addr); uint32_t _p = (parity); uint32_t _d;               \
    asm volatile("{\n\t.reg .pred p;\n\t"                                         \
        "mbarrier.try_wait.parity.acquire.cta.shared::cta.b64 p, [%1], %2;\n\t"   \
        "selp.b32 %0, 1, 0, p;\n\t}" : "=r"(_d) : "r"(_m), "r"(_p) : "memory");   \
    if (!_d) {                                                                    \
        asm volatile("{\n\t.reg .pred P1;\n\t"                                    \
            "WL_%=:\n\t"                                                          \
            "mbarrier.try_wait.parity.acquire.cta.shared::cta.b64 P1, [%0], %1, 0x989680;\n\t" \
            "@P1 bra.uni WD_%=;\n\t"                                              \
            "bra.uni WL_%=;\n\t"                                                  \
            "WD_%=:\n\t}" :: "r"(_m), "r"(_p) : "memory");                        \
    }                                                                             \
} while (0)

#define LDTM_X32(r, tmem_addr)                                                    \
    asm volatile("tcgen05.ld.sync.aligned.32x32b.x32.b32 "                        \
        "{%0, %1, %2, %3, %4, %5, %6, %7, %8, %9, %10, %11, %12, %13, %14, %15, " \
        " %16, %17, %18, %19, %20, %21, %22, %23, %24, %25, %26, %27, %28, %29, %30, %31}, [%32];" \
        : "=r"((r)[0]),  "=r"((r)[1]),  "=r"((r)[2]),  "=r"((r)[3]),              \
          "=r"((r)[4]),  "=r"((r)[5]),  "=r"((r)[6]),  "=r"((r)[7]),              \
          "=r"((r)[8]),  "=r"((r)[9]),  "=r"((r)[10]), "=r"((r)[11]),             \
          "=r"((r)[12]), "=r"((r)[13]), "=r"((r)[14]), "=r"((r)[15]),             \
          "=r"((r)[16]), "=r"((r)[17]), "=r"((r)[18]), "=r"((r)[19]),             \
          "=r"((r)[20]), "=r"((r)[21]), "=r"((r)[22]), "=r"((r)[23]),             \
          "=r"((r)[24]), "=r"((r)[25]), "=r"((r)[26]), "=r"((r)[27]),             \
          "=r"((r)[28]), "=r"((r)[29]), "=r"((r)[30]), "=r"((r)[31])              \
        : "r"(tmem_addr))

#endif // HAS_TCGEN05

// ---------------- prep: x->bf16 + column partials, and W^T ----------------
__global__ void k_prep(const float* __restrict__ x, const float* __restrict__ w) {
    if (blockIdx.x < 1024) {
        int c = threadIdx.x;                 // 0..127
        int blk = blockIdx.x;
        int r0 = blk * 98;
        int r1 = r0 + 98; if (r1 > NROWS) r1 = NROWS;
        float acc = 0.f;
        #pragma unroll 4
        for (int r = r0; r < r1; ++r) {
            float v = x[(size_t)r * DIM + c];
            acc += v;
            g_xb[(size_t)r * DIM + c] = __float2bfloat16(v);
        }
        g_partial[blk][c] = acc;
    } else {
        int base = (blockIdx.x - 1024) * 4096;           // 12 blocks cover 49152
        for (int j = threadIdx.x; j < 4096; j += 128) {
            int i = base + j;
            int n = i / KTOT, k = i - n * KTOT;
            g_wtb[i] = __float2bfloat16(w[(size_t)k * DOUT + n]);
        }
    }
}

// ---------------- pool row ----------------
__global__ void k_pool2(const float* __restrict__ w) {
    __shared__ float red[128];
    int n = blockIdx.x, d = threadIdx.x;
    float s = 0.f;
    #pragma unroll 8
    for (int b = 0; b < 1024; ++b) s += g_partial[b][d];
    red[d] = s * w[(size_t)(KTOT + d) * DOUT + n];
    __syncthreads();
    if (d == 0) {
        float t = 0.f;
        #pragma unroll 8
        for (int i = 0; i < 128; ++i) t += red[i];
        g_pool[n] = t;
    }
}

// ---------------- main persistent pipelined gather-GEMM ----------------
#define SMEM_TMEM  0
#define SMEM_MBAR  8
#define SMEM_POOL  64                          // 64..576
#define SMEM_A     2048                        // 6 x 16384 -> 100352
#define CHUNK_B    16384
#define SMEM_W     100352                      // -> 198656
#define SMEM_STG0  198656                      // 16 KB
#define SMEM_STG1  215040                      // 16 KB -> 231424
#define DYN_SMEM   232448                      // 227 KB (max)

static constexpr uint32_t IDESC_F16 =
    (1u << 4) | (1u << 7) | (1u << 10) | ((DOUT / 8) << 17) | ((128 / 16) << 24);

#if HAS_TCGEN05
// Gather directly from global idx (16-lane broadcast loads), clamp, batch LDG.128.
__device__ __forceinline__ void issue_gathers(const int* __restrict__ idx,
                                              long long tile, uint4* gv,
                                              int wid, int half, int hl) {
    int xr[24];
    #pragma unroll
    for (int s = 0; s < 3; ++s)
        #pragma unroll
        for (int it = 0; it < 8; ++it) {
            int m = (wid + it * 8) * 2 + half;
            long long b = tile * 128 + m;
            if (b >= BTOT) b = BTOT - 1;
            xr[s * 8 + it] = idx[b * 3 + s];
        }
    #pragma unroll
    for (int i = 0; i < 24; ++i) {
        int v = xr[i];
        if (v < 0) v = 0;
        if (v >= NROWS) v = NROWS - 1;
        gv[i] = *(const uint4*)((const char*)g_xb + (size_t)v * 256 + hl * 16);
    }
}

// Epilogue: 4 x (LDTM 32 cols + pool-add -> SW128 staging -> TMA bulk store)
__device__ __forceinline__ void do_epilogue(char* sm, uint32_t sb, uint32_t dbase,
                                            long long tile, const CUtensorMap* tmap,
                                            int tid) {
    const float* spool = (const float*)(sm + SMEM_POOL);
    #pragma unroll
    for (int b = 0; b < 4; ++b) {
        const uint32_t stg = (b & 1) ? SMEM_STG1 : SMEM_STG0;
        float4 o[8];
        if (tid < 128) {
            uint32_t r[32];
            LDTM_X32(r, dbase + b * 32);
            TC_WAIT_LD();
            #pragma unroll
            for (int q = 0; q < 8; ++q) {
                float4 pv = *(const float4*)(spool + b * 32 + q * 4);
                o[q].x = __uint_as_float(r[q * 4 + 0]) + pv.x;
                o[q].y = __uint_as_float(r[q * 4 + 1]) + pv.y;
                o[q].z = __uint_as_float(r[q * 4 + 2]) + pv.z;
                o[q].w = __uint_as_float(r[q * 4 + 3]) + pv.w;
            }
        }
        if (tid == 0) TMA_WAIT1();            // staging buffer (b&1) free
        __syncthreads();
        if (tid < 128) {
            #pragma unroll
            for (int q = 0; q < 8; ++q)
                *(float4*)(sm + stg + SW128((uint32_t)tid * 128 + q * 16)) = o[q];
        }
        __syncthreads();
        if (tid == 0) {
            FENCE_PROXY();
            asm volatile(
                "cp.async.bulk.tensor.2d.global.shared::cta.tile.bulk_group "
                "[%0, {%1, %2}], [%3];"
                :: "l"(tmap), "r"(b * 32), "r"((int)(tile * 128)), "r"(sb + stg)
                : "memory");
            TMA_COMMIT();
        }
    }
    if (tid < 128) TC_FENCE_BEFORE();
}
#endif

__global__ void __launch_bounds__(256, 1) __cluster_dims__(1, 1, 1)
k_main(const int* __restrict__ idx, float* __restrict__ out,
       const __grid_constant__ CUtensorMap tmap) {
#if HAS_TCGEN05
    extern __shared__ char smraw[];
    uint32_t sb0 = smem_u32(smraw);
    uint32_t sb = (sb0 + 1023u) & ~1023u;
    char* sm = smraw + (sb - sb0);
    int tid = threadIdx.x, wid = tid >> 5, lane = tid & 31;

    if (wid == 0) TC_ALLOC(sb + SMEM_TMEM, 512);
    else          TC_RELINQ();
    if (tid == 0) MBAR_INIT(sb + SMEM_MBAR, 1);
    if (tid < DOUT) *(float*)(sm + SMEM_POOL + tid * 4) = g_pool[tid];

    // Stage weights once: SW128 into 6 K-chunks
    for (int u = tid; u < 6144; u += 256) {
        int n = u / 48;
        int q = u - n * 48;
        int k = q * 8;
        int kc = k >> 6, kin = k & 63;
        uint4 v = *(const uint4*)((const char*)g_wtb + ((size_t)n * KTOT + k) * 2);
        uint32_t off = (uint32_t)n * 128 + (uint32_t)kin * 2;
        *(uint4*)(sm + SMEM_W + kc * CHUNK_B + SW128(off)) = v;
    }
    __syncthreads();
    uint32_t tmem_base = *(volatile uint32_t*)(sm + SMEM_TMEM);

    const int n_tiles = (BTOT + 127) >> 7;         // 3907
    int phase = 0;
    int bufp = 0;
    long long prev_tile = -1;
    int prevp = 0;

    const int half = lane >> 4, hl = lane & 15;
    const int kc_off = hl >> 3;
    const uint32_t colb = (uint32_t)(hl & 7) * 16;

    uint4 gv[24];

    // ---- prologue: issue gathers for first tile ----
    long long tile = blockIdx.x;
    if (tile < n_tiles)
        issue_gathers(idx, tile, gv, wid, half, hl);

    for (; tile < n_tiles; tile += gridDim.x) {
        long long next = tile + gridDim.x;

        // ---- 1. wait previous MMA (frees A, readies D[prevp]) ----
        if (prev_tile >= 0) {
            MBAR_WAIT(sb + SMEM_MBAR, phase);
            phase ^= 1;
            TC_FENCE_AFTER();
        }

        // ---- 2. STS gather regs -> A (swizzled) ----
        #pragma unroll
        for (int s = 0; s < 3; ++s)
            #pragma unroll
            for (int it = 0; it < 8; ++it) {
                int m = (wid + it * 8) * 2 + half;
                uint32_t off = (uint32_t)m * 128 + colb;
                *(uint4*)(sm + SMEM_A + (2 * s + kc_off) * CHUNK_B + SW128(off)) =
                    gv[s * 8 + it];
            }
        __syncthreads();

        // ---- 3. issue all 24 MMAs into D[bufp]; commit ----
        if (wid == 0 && elect_one()) {
            FENCE_PROXY();
            bool acc = false;
            #pragma unroll
            for (int kc = 0; kc < 6; ++kc) {
                uint64_t ad = make_desc(sb + SMEM_A + kc * CHUNK_B);
                uint64_t bd = make_desc(sb + SMEM_W + kc * CHUNK_B);
                #pragma unroll
                for (int ks = 0; ks < 4; ++ks) {
                    mma_f16_ss(tmem_base + bufp * 128, ad + ks * 2, bd + ks * 2,
                               IDESC_F16, acc);
                    acc = true;
                }
            }
            TC_COMMIT(sb + SMEM_MBAR);
        }

        // ---- 4. issue gathers(next); flight covered by epilogue ----
        if (next < n_tiles)
            issue_gathers(idx, next, gv, wid, half, hl);

        // ---- 5. epilogue of previous tile (overlaps MMA + gather flight) ----
        if (prev_tile >= 0)
            do_epilogue(sm, sb, tmem_base + prevp * 128, prev_tile, &tmap, tid);

        prev_tile = tile;
        prevp = bufp;
        bufp ^= 1;
    }

    // ---- drain last tile ----
    if (prev_tile >= 0) {
        MBAR_WAIT(sb + SMEM_MBAR, phase);
        phase ^= 1;
        TC_FENCE_AFTER();
        do_epilogue(sm, sb, tmem_base + prevp * 128, prev_tile, &tmap, tid);
    }
    if (tid == 0) TMA_WAIT0();                 // all TMA stores complete

    __syncthreads();
    if (tid == 0) MBAR_INVAL(sb + SMEM_MBAR);
    __syncthreads();
    if (wid == 0) TC_DEALLOC(tmem_base, 512);
#endif // HAS_TCGEN05
}

// ---------------- launcher ----------------
typedef CUresult (*encode_fn_t)(CUtensorMap*, CUtensorMapDataType, cuuint32_t, void*,
                                const cuuint64_t*, const cuuint64_t*, const cuuint32_t*,
                                const cuuint32_t*, CUtensorMapInterleave, CUtensorMapSwizzle,
                                CUtensorMapL2promotion, CUtensorMapFloatOOBfill);

extern "C" void kernel_launch(void* const* d_in, const int* in_sizes, int n_in,
                              void* d_out, int out_size) {
    const float* x = nullptr;
    const int* idx = nullptr;
    const float* w = nullptr;
    for (int i = 0; i < n_in; ++i) {
        if (in_sizes[i] == NROWS * DIM)              x   = (const float*)d_in[i];
        else if (in_sizes[i] == BTOT * 3)            idx = (const int*)d_in[i];
        else if (in_sizes[i] == (KTOT + DIM) * DOUT) w   = (const float*)d_in[i];
    }
    float* out = (float*)d_out;

    // Build TMA store descriptor for out [500000 x 128] f32, box [32,128], SW128.
    static encode_fn_t encode = nullptr;
    if (!encode) {
        cudaDriverEntryPointQueryResult qr;
        cudaGetDriverEntryPointByVersion("cuTensorMapEncodeTiled", (void**)&encode,
                                         12000, cudaEnableDefault, &qr);
    }
    static CUtensorMap tmap;
    {
        cuuint64_t dims[2]    = {(cuuint64_t)DOUT, (cuuint64_t)BTOT};
        cuuint64_t strides[1] = {(cuuint64_t)DOUT * sizeof(float)};
        cuuint32_t box[2]     = {32u, 128u};
        cuuint32_t es[2]      = {1u, 1u};
        encode(&tmap, CU_TENSOR_MAP_DATA_TYPE_FLOAT32, 2, out,
               dims, strides, box, es,
               CU_TENSOR_MAP_INTERLEAVE_NONE, CU_TENSOR_MAP_SWIZZLE_128B,
               CU_TENSOR_MAP_L2_PROMOTION_NONE, CU_TENSOR_MAP_FLOAT_OOB_FILL_NONE);
    }

    cudaFuncSetAttribute(k_main, cudaFuncAttributeMaxDynamicSharedMemorySize, DYN_SMEM);
    int nsm = 148;
    cudaDeviceGetAttribute(&nsm, cudaDevAttrMultiProcessorCount, 0);

    k_prep<<<1036, 128>>>(x, w);
    k_pool2<<<128, 128>>>(w);
    k_main<<<nsm, 256, DYN_SMEM>>>(idx, out, tmap);
}